// round 1
// baseline (speedup 1.0000x reference)
#include <cuda_runtime.h>
#include <math.h>

// Problem constants
#define NB   4
#define CC   128
#define HH   128
#define WW   256
#define HWSZ (HH * WW)          // 32768
#define NHW  (NB * HWSZ)        // 131072
#define DIM  128
#define NWP  4

// Device-global scratch (allocation-free per harness rules)
__device__ float g_K[(size_t)NHW * DIM];
__device__ float g_V[(size_t)NHW * DIM];
__device__ float g_Q[(size_t)NHW * DIM];
__device__ float g_kb[NWP * DIM];
__device__ float g_vb[NWP * DIM];

// 10000^(-t2/32), t2 in [0,32): inverse of the paired dim_t frequency
__device__ __forceinline__ float inv_dt(int t2) {
    // log2(10000) = 13.287712379549449
    return exp2f(-(float)t2 * (13.287712379549449f / 32.0f));
}

// ---------------------------------------------------------------------------
// Kernel 0: window position-bias projections
//   g_kb[w][d] = pb[w] @ k_w + k_b ;  g_vb[w][d] = pb[w] @ v_w + v_b
// pb[w] = sine PE of window offset (oy, ox) in {0,1}^2
// ---------------------------------------------------------------------------
__global__ void bias_kernel(const float* __restrict__ kw, const float* __restrict__ kb,
                            const float* __restrict__ vw, const float* __restrict__ vb) {
    __shared__ float pb[NWP * DIM];
    int t = threadIdx.x;                  // 0..511
    {
        int w  = t >> 7;
        int i  = t & 127;
        int oy = w >> 1, ox = w & 1;
        float coord = (i < 64) ? (float)oy : (float)ox;
        int ii = i & 63;
        int t2 = ii >> 1;
        // norm = coord / (coord[-1] + eps) * 2*pi ; coord[-1] = WS-1 = 1
        float arg = coord * (6.283185307179586f / 1.000001f) * inv_dt(t2);
        float s, c;
        sincosf(arg, &s, &c);
        pb[t] = (ii & 1) ? c : s;
    }
    __syncthreads();
    int w = t >> 7, d = t & 127;
    float accK = 0.f, accV = 0.f;
    const float* pbr = pb + w * DIM;
#pragma unroll 8
    for (int c = 0; c < DIM; ++c) {
        float p = pbr[c];
        accK += p * kw[c * DIM + d];
        accV += p * vw[c * DIM + d];
    }
    g_kb[t] = accK + kb[d];
    g_vb[t] = accV + vb[d];
}

// ---------------------------------------------------------------------------
// Shared GEMM tile machinery: 128(M-pixels) x 128(N) x 128(K), 256 threads,
// 8x8 register microtile per thread, A and B fully resident in dynamic smem.
// As layout: [k][m] (k-major), Bs layout: [k][d].
// ---------------------------------------------------------------------------
__device__ __forceinline__ void gemm_tile_compute(const float* __restrict__ As,
                                                  const float* __restrict__ Bs,
                                                  float acc[8][8], int tx, int ty) {
#pragma unroll 4
    for (int k = 0; k < 128; ++k) {
        float4 a0 = *(const float4*)(As + k * 128 + ty * 4);
        float4 a1 = *(const float4*)(As + k * 128 + 64 + ty * 4);
        float4 b0 = *(const float4*)(Bs + k * 128 + tx * 4);
        float4 b1 = *(const float4*)(Bs + k * 128 + 64 + tx * 4);
        float a[8] = {a0.x, a0.y, a0.z, a0.w, a1.x, a1.y, a1.z, a1.w};
        float b[8] = {b0.x, b0.y, b0.z, b0.w, b1.x, b1.y, b1.z, b1.w};
#pragma unroll
        for (int i = 0; i < 8; ++i)
#pragma unroll
            for (int j = 0; j < 8; ++j)
                acc[i][j] += a[i] * b[j];
    }
}

__device__ __forceinline__ void write_tile(float* __restrict__ out, int m0,
                                           float acc[8][8], int tx, int ty,
                                           const float* __restrict__ bias) {
    float bj[8];
#pragma unroll
    for (int j = 0; j < 4; ++j) {
        bj[j]     = bias ? bias[tx * 4 + j]      : 0.f;
        bj[4 + j] = bias ? bias[64 + tx * 4 + j] : 0.f;
    }
#pragma unroll
    for (int i = 0; i < 8; ++i) {
        int r = (i < 4) ? (ty * 4 + i) : (64 + ty * 4 + (i - 4));
        float* p = out + (size_t)(m0 + r) * DIM;
        float4 o0 = make_float4(acc[i][0] + bj[0], acc[i][1] + bj[1],
                                acc[i][2] + bj[2], acc[i][3] + bj[3]);
        float4 o1 = make_float4(acc[i][4] + bj[4], acc[i][5] + bj[5],
                                acc[i][6] + bj[6], acc[i][7] + bj[7]);
        *(float4*)(p + tx * 4)      = o0;
        *(float4*)(p + 64 + tx * 4) = o1;
    }
}

// ---------------------------------------------------------------------------
// Kernel 1: g_K = feat_supp @ k_w ; g_V = feat_supp @ v_w  (no biases here;
// they live in g_kb/g_vb). A-tile loaded once, both GEMMs computed.
// feat layout: (n, c, h, w) -> A[m][c] = feat[(n*C + c)*HW + pix]
// ---------------------------------------------------------------------------
__global__ void gemm_kv_kernel(const float* __restrict__ feat,
                               const float* __restrict__ kw,
                               const float* __restrict__ vw) {
    extern __shared__ float sm[];
    float* As = sm;               // 128*128
    float* Bs = sm + 128 * 128;   // 128*128
    int t  = threadIdx.x;
    int m0 = blockIdx.x * 128;
    int n    = m0 / HWSZ;
    int pix0 = m0 % HWSZ;

#pragma unroll 4
    for (int j = 0; j < 64; ++j) {
        int li = j * 256 + t;
        int c = li >> 7, m = li & 127;
        As[c * 128 + m] = feat[(size_t)(n * CC + c) * HWSZ + pix0 + m];
    }
#pragma unroll 4
    for (int j = 0; j < 64; ++j) {
        int li = j * 256 + t;
        Bs[li] = kw[li];
    }
    __syncthreads();

    int tx = t & 15, ty = t >> 4;
    float acc[8][8];
#pragma unroll
    for (int i = 0; i < 8; ++i)
#pragma unroll
        for (int j = 0; j < 8; ++j) acc[i][j] = 0.f;

    gemm_tile_compute(As, Bs, acc, tx, ty);
    write_tile(g_K, m0, acc, tx, ty, nullptr);
    __syncthreads();

#pragma unroll 4
    for (int j = 0; j < 64; ++j) {
        int li = j * 256 + t;
        Bs[li] = vw[li];
    }
    __syncthreads();

#pragma unroll
    for (int i = 0; i < 8; ++i)
#pragma unroll
        for (int j = 0; j < 8; ++j) acc[i][j] = 0.f;

    gemm_tile_compute(As, Bs, acc, tx, ty);
    write_tile(g_V, m0, acc, tx, ty, nullptr);
}

// ---------------------------------------------------------------------------
// Kernel 2: g_Q = (feat_curr + PE(frac(flow))) @ q_w + q_b
// PE added into the A-tile in smem: 2 threads per pixel (y-half / x-half).
// ---------------------------------------------------------------------------
__global__ void gemm_q_kernel(const float* __restrict__ feat,
                              const float* __restrict__ flow,
                              const float* __restrict__ qw,
                              const float* __restrict__ qb) {
    extern __shared__ float sm[];
    float* As = sm;
    float* Bs = sm + 128 * 128;
    int t  = threadIdx.x;
    int m0 = blockIdx.x * 128;
    int n    = m0 / HWSZ;
    int pix0 = m0 % HWSZ;

#pragma unroll 4
    for (int j = 0; j < 64; ++j) {
        int li = j * 256 + t;
        int c = li >> 7, m = li & 127;
        As[c * 128 + m] = feat[(size_t)(n * CC + c) * HWSZ + pix0 + m];
    }
#pragma unroll 4
    for (int j = 0; j < 64; ++j) {
        int li = j * 256 + t;
        Bs[li] = qw[li];
    }
    __syncthreads();

    // Add per-pixel sine PE of the fractional flow target into As
    {
        int m    = t >> 1;
        int half = t & 1;                       // 0: y-part (dims 0..63), 1: x-part
        int pix  = pix0 + m;
        int y = pix / WW, x = pix % WW;
        const float* fl = flow + (size_t)((n * HH + y) * WW + x) * 2;
        float fx = fl[0], fy = fl[1];           // flow flip: full=(y+fy, x+fx)
        float full = half ? ((float)x + fx) : ((float)y + fy);
        float dec  = full - floorf(full);
        float base = dec * (6.283185307179586f / 2.000001f);  // /(WS+eps)*2pi
        int coff = half * 64;
#pragma unroll
        for (int t2 = 0; t2 < 32; ++t2) {
            float arg = base * inv_dt(t2);
            float s, c;
            sincosf(arg, &s, &c);
            As[(coff + 2 * t2)     * 128 + m] += s;
            As[(coff + 2 * t2 + 1) * 128 + m] += c;
        }
    }
    __syncthreads();

    int tx = t & 15, ty = t >> 4;
    float acc[8][8];
#pragma unroll
    for (int i = 0; i < 8; ++i)
#pragma unroll
        for (int j = 0; j < 8; ++j) acc[i][j] = 0.f;

    gemm_tile_compute(As, Bs, acc, tx, ty);
    write_tile(g_Q, m0, acc, tx, ty, qb);
}

// ---------------------------------------------------------------------------
// Kernel 3: per-pixel attention. One warp per pixel, 8 pixels per CTA.
// Lane l owns channels [4l, 4l+4). Head h = lanes 4h..4h+3 (16 channels).
// Output staged in smem and written channel-major coalesced.
// ---------------------------------------------------------------------------
__global__ void attn_kernel(const float* __restrict__ flow, float* __restrict__ out) {
    __shared__ float s_out[8][132];
    __shared__ float s_kb[NWP * DIM];
    __shared__ float s_vb[NWP * DIM];
    int t = threadIdx.x;
    for (int i = t; i < NWP * DIM; i += 256) {
        s_kb[i] = g_kb[i];
        s_vb[i] = g_vb[i];
    }
    __syncthreads();

    int warp = t >> 5, lane = t & 31;
    int p   = blockIdx.x * 8 + warp;
    int n   = p / HWSZ;
    int pix = p % HWSZ;
    int y = pix / WW, x = pix % WW;

    const float* fl = flow + (size_t)((n * HH + y) * WW + x) * 2;
    float fx = fl[0], fy = fl[1];
    int giy = (int)floorf((float)y + fy);
    int gix = (int)floorf((float)x + fx);

    int c0 = lane * 4;
    float4 q = *(const float4*)(g_Q + (size_t)p * DIM + c0);
    const float sc = 0.25f;                       // (DIM/HEADS)^-0.5
    q.x *= sc; q.y *= sc; q.z *= sc; q.w *= sc;

    int   nb[4];
    float lg[4];
#pragma unroll
    for (int w2 = 0; w2 < 4; ++w2) {
        int hy = giy + (w2 >> 1);
        int wx = gix + (w2 & 1);
        hy = hy < 0 ? 0 : (hy > HH - 1 ? HH - 1 : hy);
        wx = wx < 0 ? 0 : (wx > WW - 1 ? WW - 1 : wx);
        nb[w2] = n * HWSZ + hy * WW + wx;
        float4 k = *(const float4*)(g_K + (size_t)nb[w2] * DIM + c0);
        const float* kbp = s_kb + w2 * DIM + c0;
        float part = q.x * (k.x + kbp[0]) + q.y * (k.y + kbp[1]) +
                     q.z * (k.z + kbp[2]) + q.w * (k.w + kbp[3]);
        part += __shfl_xor_sync(0xffffffffu, part, 1);
        part += __shfl_xor_sync(0xffffffffu, part, 2);
        lg[w2] = part;
    }
    float mx = fmaxf(fmaxf(lg[0], lg[1]), fmaxf(lg[2], lg[3]));
    float e0 = expf(lg[0] - mx), e1 = expf(lg[1] - mx);
    float e2 = expf(lg[2] - mx), e3 = expf(lg[3] - mx);
    float inv = 1.f / (e0 + e1 + e2 + e3);
    float aw[4] = {e0 * inv, e1 * inv, e2 * inv, e3 * inv};

    float4 o = make_float4(0.f, 0.f, 0.f, 0.f);
#pragma unroll
    for (int w2 = 0; w2 < 4; ++w2) {
        float4 v = *(const float4*)(g_V + (size_t)nb[w2] * DIM + c0);
        const float* vbp = s_vb + w2 * DIM + c0;
        float a = aw[w2];
        o.x += a * (v.x + vbp[0]);
        o.y += a * (v.y + vbp[1]);
        o.z += a * (v.z + vbp[2]);
        o.w += a * (v.w + vbp[3]);
    }
    s_out[warp][c0 + 0] = o.x;
    s_out[warp][c0 + 1] = o.y;
    s_out[warp][c0 + 2] = o.z;
    s_out[warp][c0 + 3] = o.w;
    __syncthreads();

    // Coalesced channel-major write: out[n][d][y][x]
    int p0   = blockIdx.x * 8;
    int n0   = p0 / HWSZ;
    int pix0 = p0 % HWSZ;
    int y0 = pix0 / WW, x0 = pix0 % WW;
#pragma unroll
    for (int rep = 0; rep < 4; ++rep) {
        int d  = (t >> 3) + rep * 32;
        int px = t & 7;
        out[((size_t)(n0 * DIM + d) * HH + y0) * WW + x0 + px] = s_out[px][d];
    }
}

// ---------------------------------------------------------------------------
extern "C" void kernel_launch(void* const* d_in, const int* in_sizes, int n_in,
                              void* d_out, int out_size) {
    const float* feat_supp = (const float*)d_in[0];
    const float* feat_curr = (const float*)d_in[1];
    const float* flow      = (const float*)d_in[2];
    const float* q_w       = (const float*)d_in[3];
    const float* q_b       = (const float*)d_in[4];
    const float* k_w       = (const float*)d_in[5];
    const float* k_b       = (const float*)d_in[6];
    const float* v_w       = (const float*)d_in[7];
    const float* v_b       = (const float*)d_in[8];
    float* out = (float*)d_out;

    const int smem_bytes = 2 * 128 * 128 * (int)sizeof(float);  // 128 KB
    cudaFuncSetAttribute(gemm_kv_kernel, cudaFuncAttributeMaxDynamicSharedMemorySize, smem_bytes);
    cudaFuncSetAttribute(gemm_q_kernel,  cudaFuncAttributeMaxDynamicSharedMemorySize, smem_bytes);

    bias_kernel<<<1, 512>>>(k_w, k_b, v_w, v_b);
    gemm_kv_kernel<<<NHW / 128, 256, smem_bytes>>>(feat_supp, k_w, v_w);
    gemm_q_kernel<<<NHW / 128, 256, smem_bytes>>>(feat_curr, flow, q_w, q_b);
    attn_kernel<<<NHW / 8, 256>>>(flow, out);
}

// round 2
// speedup vs baseline: 1.8701x; 1.8701x over previous
#include <cuda_runtime.h>
#include <math.h>
#include <stdint.h>

// Problem constants
#define NB   4
#define CC   128
#define HH   128
#define WW   256
#define HWSZ (HH * WW)          // 32768
#define NHW  (NB * HWSZ)        // 131072
#define DIM  128
#define NWP  4
#define PAD  136                // smem row pitch (words); 136%32==8 -> conflict-free frags

// Device-global scratch (allocation-free per harness rules)
__device__ float g_K[(size_t)NHW * DIM];
__device__ float g_V[(size_t)NHW * DIM];
__device__ float g_Q[(size_t)NHW * DIM];
__device__ float g_kb[NWP * DIM];
__device__ float g_vb[NWP * DIM];

// 10000^(-t2/32)
__device__ __forceinline__ float inv_dt(int t2) {
    return exp2f(-(float)t2 * (13.287712379549449f / 32.0f));
}

__device__ __forceinline__ uint32_t f2tf32(float x) {
    uint32_t u;
    asm("cvt.rna.tf32.f32 %0, %1;" : "=r"(u) : "f"(x));
    return u;
}

__device__ __forceinline__ void mma_tf32(float d[4], const uint32_t a[4],
                                         uint32_t b0, uint32_t b1) {
    asm volatile(
        "mma.sync.aligned.m16n8k8.row.col.f32.tf32.tf32.f32 "
        "{%0,%1,%2,%3}, {%4,%5,%6,%7}, {%8,%9}, {%0,%1,%2,%3};\n"
        : "+f"(d[0]), "+f"(d[1]), "+f"(d[2]), "+f"(d[3])
        : "r"(a[0]), "r"(a[1]), "r"(a[2]), "r"(a[3]), "r"(b0), "r"(b1));
}

// ---------------------------------------------------------------------------
// Kernel 0: window position-bias projections (tiny, unchanged)
// ---------------------------------------------------------------------------
__global__ void bias_kernel(const float* __restrict__ kw, const float* __restrict__ kb,
                            const float* __restrict__ vw, const float* __restrict__ vb) {
    __shared__ float pb[NWP * DIM];
    int t = threadIdx.x;                  // 0..511
    {
        int w  = t >> 7;
        int i  = t & 127;
        int oy = w >> 1, ox = w & 1;
        float coord = (i < 64) ? (float)oy : (float)ox;
        int ii = i & 63;
        int t2 = ii >> 1;
        float arg = coord * (6.283185307179586f / 1.000001f) * inv_dt(t2);
        float s, c;
        sincosf(arg, &s, &c);
        pb[t] = (ii & 1) ? c : s;
    }
    __syncthreads();
    int w = t >> 7, d = t & 127;
    float accK = 0.f, accV = 0.f;
    const float* pbr = pb + w * DIM;
#pragma unroll 8
    for (int c = 0; c < DIM; ++c) {
        float p = pbr[c];
        accK += p * kw[c * DIM + d];
        accV += p * vw[c * DIM + d];
    }
    g_kb[t] = accK + kb[d];
    g_vb[t] = accV + vb[d];
}

// ---------------------------------------------------------------------------
// Kernel 1: g_K = feat_supp @ k_w ; g_V = feat_supp @ v_w  via tf32 mma.sync.
// CTA: 512 threads (16 warps), tile M=128 x N=128 x K=128.
// Warp w: rows (w&3)*32..+32, cols (w>>2)*32..+32, microtiled m16n8k8.
// SMEM: As[k][m] pad 136, Bk[k][d] pad 136, Bv[k][d] pad 136.
// ---------------------------------------------------------------------------
__global__ __launch_bounds__(512, 1)
void gemm_kv_kernel(const float* __restrict__ feat,
                    const float* __restrict__ kw,
                    const float* __restrict__ vw) {
    extern __shared__ float sm[];
    float* As = sm;
    float* Bk = sm + 128 * PAD;
    float* Bv = sm + 2 * 128 * PAD;
    int t  = threadIdx.x;
    int m0 = blockIdx.x * 128;
    int n    = m0 / HWSZ;
    int pix0 = m0 % HWSZ;

#pragma unroll 4
    for (int j = 0; j < 32; ++j) {
        int li = j * 512 + t;
        int c = li >> 7, m = li & 127;
        As[c * PAD + m] = feat[(size_t)(n * CC + c) * HWSZ + pix0 + m];
    }
#pragma unroll 4
    for (int j = 0; j < 32; ++j) {
        int li = j * 512 + t;
        int c = li >> 7, d = li & 127;
        Bk[c * PAD + d] = kw[li];
        Bv[c * PAD + d] = vw[li];
    }
    __syncthreads();

    int w = t >> 5, lane = t & 31;
    int m0w = (w & 3) * 32, n0w = (w >> 2) * 32;
    int q = lane & 3, g = lane >> 2;

    float accK[2][4][4];
    float accV[2][4][4];
#pragma unroll
    for (int mi = 0; mi < 2; ++mi)
#pragma unroll
        for (int nj = 0; nj < 4; ++nj)
#pragma unroll
            for (int e = 0; e < 4; ++e) { accK[mi][nj][e] = 0.f; accV[mi][nj][e] = 0.f; }

#pragma unroll
    for (int kk = 0; kk < 16; ++kk) {
        int k0 = kk * 8;
        uint32_t a[2][4];
#pragma unroll
        for (int mi = 0; mi < 2; ++mi) {
            int m = m0w + mi * 16 + g;
            a[mi][0] = f2tf32(As[(k0 + q) * PAD + m]);
            a[mi][1] = f2tf32(As[(k0 + q) * PAD + m + 8]);
            a[mi][2] = f2tf32(As[(k0 + q + 4) * PAD + m]);
            a[mi][3] = f2tf32(As[(k0 + q + 4) * PAD + m + 8]);
        }
#pragma unroll
        for (int nj = 0; nj < 4; ++nj) {
            int nn = n0w + nj * 8 + g;
            uint32_t bk0 = f2tf32(Bk[(k0 + q) * PAD + nn]);
            uint32_t bk1 = f2tf32(Bk[(k0 + q + 4) * PAD + nn]);
            uint32_t bv0 = f2tf32(Bv[(k0 + q) * PAD + nn]);
            uint32_t bv1 = f2tf32(Bv[(k0 + q + 4) * PAD + nn]);
#pragma unroll
            for (int mi = 0; mi < 2; ++mi) {
                mma_tf32(accK[mi][nj], a[mi], bk0, bk1);
                mma_tf32(accV[mi][nj], a[mi], bv0, bv1);
            }
        }
    }

#pragma unroll
    for (int mi = 0; mi < 2; ++mi) {
#pragma unroll
        for (int nj = 0; nj < 4; ++nj) {
            int r0 = m0 + m0w + mi * 16 + g;
            int cb = n0w + nj * 8 + q * 2;
            *(float2*)(g_K + (size_t)r0 * DIM + cb) =
                make_float2(accK[mi][nj][0], accK[mi][nj][1]);
            *(float2*)(g_K + (size_t)(r0 + 8) * DIM + cb) =
                make_float2(accK[mi][nj][2], accK[mi][nj][3]);
            *(float2*)(g_V + (size_t)r0 * DIM + cb) =
                make_float2(accV[mi][nj][0], accV[mi][nj][1]);
            *(float2*)(g_V + (size_t)(r0 + 8) * DIM + cb) =
                make_float2(accV[mi][nj][2], accV[mi][nj][3]);
        }
    }
}

// ---------------------------------------------------------------------------
// Kernel 2: g_Q = (feat_curr + PE(frac(flow))) @ q_w + q_b  (tf32 mma.sync)
// ---------------------------------------------------------------------------
__global__ __launch_bounds__(512, 1)
void gemm_q_kernel(const float* __restrict__ feat,
                   const float* __restrict__ flow,
                   const float* __restrict__ qw,
                   const float* __restrict__ qb) {
    extern __shared__ float sm[];
    float* As = sm;
    float* Bs = sm + 128 * PAD;
    int t  = threadIdx.x;
    int m0 = blockIdx.x * 128;
    int n    = m0 / HWSZ;
    int pix0 = m0 % HWSZ;

#pragma unroll 4
    for (int j = 0; j < 32; ++j) {
        int li = j * 512 + t;
        int c = li >> 7, m = li & 127;
        As[c * PAD + m] = feat[(size_t)(n * CC + c) * HWSZ + pix0 + m];
    }
#pragma unroll 4
    for (int j = 0; j < 32; ++j) {
        int li = j * 512 + t;
        int c = li >> 7, d = li & 127;
        Bs[c * PAD + d] = qw[li];
    }
    __syncthreads();

    // Per-pixel sine PE of fractional flow target, added into As.
    // Threads 0..255: 2 per pixel (half 0 = y dims 0..63, half 1 = x dims 64..127).
    if (t < 256) {
        int m    = t >> 1;
        int half = t & 1;
        int pix  = pix0 + m;
        int y = pix / WW, x = pix % WW;
        const float* fl = flow + (size_t)((n * HH + y) * WW + x) * 2;
        float fx = fl[0], fy = fl[1];
        float full = half ? ((float)x + fx) : ((float)y + fy);
        float dec  = full - floorf(full);
        float base = dec * (6.283185307179586f / 2.000001f);
        int coff = half * 64;
#pragma unroll
        for (int t2 = 0; t2 < 32; ++t2) {
            float arg = base * inv_dt(t2);
            float s, c;
            sincosf(arg, &s, &c);
            As[(coff + 2 * t2)     * PAD + m] += s;
            As[(coff + 2 * t2 + 1) * PAD + m] += c;
        }
    }
    __syncthreads();

    int w = t >> 5, lane = t & 31;
    int m0w = (w & 3) * 32, n0w = (w >> 2) * 32;
    int q = lane & 3, g = lane >> 2;

    float acc[2][4][4];
#pragma unroll
    for (int mi = 0; mi < 2; ++mi)
#pragma unroll
        for (int nj = 0; nj < 4; ++nj)
#pragma unroll
            for (int e = 0; e < 4; ++e) acc[mi][nj][e] = 0.f;

#pragma unroll
    for (int kk = 0; kk < 16; ++kk) {
        int k0 = kk * 8;
        uint32_t a[2][4];
#pragma unroll
        for (int mi = 0; mi < 2; ++mi) {
            int m = m0w + mi * 16 + g;
            a[mi][0] = f2tf32(As[(k0 + q) * PAD + m]);
            a[mi][1] = f2tf32(As[(k0 + q) * PAD + m + 8]);
            a[mi][2] = f2tf32(As[(k0 + q + 4) * PAD + m]);
            a[mi][3] = f2tf32(As[(k0 + q + 4) * PAD + m + 8]);
        }
#pragma unroll
        for (int nj = 0; nj < 4; ++nj) {
            int nn = n0w + nj * 8 + g;
            uint32_t b0 = f2tf32(Bs[(k0 + q) * PAD + nn]);
            uint32_t b1 = f2tf32(Bs[(k0 + q + 4) * PAD + nn]);
#pragma unroll
            for (int mi = 0; mi < 2; ++mi)
                mma_tf32(acc[mi][nj], a[mi], b0, b1);
        }
    }

#pragma unroll
    for (int mi = 0; mi < 2; ++mi) {
#pragma unroll
        for (int nj = 0; nj < 4; ++nj) {
            int r0 = m0 + m0w + mi * 16 + g;
            int cb = n0w + nj * 8 + q * 2;
            float b0 = qb[cb], b1 = qb[cb + 1];
            *(float2*)(g_Q + (size_t)r0 * DIM + cb) =
                make_float2(acc[mi][nj][0] + b0, acc[mi][nj][1] + b1);
            *(float2*)(g_Q + (size_t)(r0 + 8) * DIM + cb) =
                make_float2(acc[mi][nj][2] + b0, acc[mi][nj][3] + b1);
        }
    }
}

// ---------------------------------------------------------------------------
// Kernel 3: per-pixel attention (unchanged from R1 — 73.8us, memory-bound)
// ---------------------------------------------------------------------------
__global__ void attn_kernel(const float* __restrict__ flow, float* __restrict__ out) {
    __shared__ float s_out[8][132];
    __shared__ float s_kb[NWP * DIM];
    __shared__ float s_vb[NWP * DIM];
    int t = threadIdx.x;
    for (int i = t; i < NWP * DIM; i += 256) {
        s_kb[i] = g_kb[i];
        s_vb[i] = g_vb[i];
    }
    __syncthreads();

    int warp = t >> 5, lane = t & 31;
    int p   = blockIdx.x * 8 + warp;
    int n   = p / HWSZ;
    int pix = p % HWSZ;
    int y = pix / WW, x = pix % WW;

    const float* fl = flow + (size_t)((n * HH + y) * WW + x) * 2;
    float fx = fl[0], fy = fl[1];
    int giy = (int)floorf((float)y + fy);
    int gix = (int)floorf((float)x + fx);

    int c0 = lane * 4;
    float4 qv = *(const float4*)(g_Q + (size_t)p * DIM + c0);
    const float sc = 0.25f;
    qv.x *= sc; qv.y *= sc; qv.z *= sc; qv.w *= sc;

    int   nb[4];
    float lg[4];
#pragma unroll
    for (int w2 = 0; w2 < 4; ++w2) {
        int hy = giy + (w2 >> 1);
        int wx = gix + (w2 & 1);
        hy = hy < 0 ? 0 : (hy > HH - 1 ? HH - 1 : hy);
        wx = wx < 0 ? 0 : (wx > WW - 1 ? WW - 1 : wx);
        nb[w2] = n * HWSZ + hy * WW + wx;
        float4 k = *(const float4*)(g_K + (size_t)nb[w2] * DIM + c0);
        const float* kbp = s_kb + w2 * DIM + c0;
        float part = qv.x * (k.x + kbp[0]) + qv.y * (k.y + kbp[1]) +
                     qv.z * (k.z + kbp[2]) + qv.w * (k.w + kbp[3]);
        part += __shfl_xor_sync(0xffffffffu, part, 1);
        part += __shfl_xor_sync(0xffffffffu, part, 2);
        lg[w2] = part;
    }
    float mx = fmaxf(fmaxf(lg[0], lg[1]), fmaxf(lg[2], lg[3]));
    float e0 = expf(lg[0] - mx), e1 = expf(lg[1] - mx);
    float e2 = expf(lg[2] - mx), e3 = expf(lg[3] - mx);
    float inv = 1.f / (e0 + e1 + e2 + e3);
    float aw[4] = {e0 * inv, e1 * inv, e2 * inv, e3 * inv};

    float4 o = make_float4(0.f, 0.f, 0.f, 0.f);
#pragma unroll
    for (int w2 = 0; w2 < 4; ++w2) {
        float4 v = *(const float4*)(g_V + (size_t)nb[w2] * DIM + c0);
        const float* vbp = s_vb + w2 * DIM + c0;
        float a = aw[w2];
        o.x += a * (v.x + vbp[0]);
        o.y += a * (v.y + vbp[1]);
        o.z += a * (v.z + vbp[2]);
        o.w += a * (v.w + vbp[3]);
    }
    s_out[warp][c0 + 0] = o.x;
    s_out[warp][c0 + 1] = o.y;
    s_out[warp][c0 + 2] = o.z;
    s_out[warp][c0 + 3] = o.w;
    __syncthreads();

    int p0   = blockIdx.x * 8;
    int n0   = p0 / HWSZ;
    int pix0 = p0 % HWSZ;
    int y0 = pix0 / WW, x0 = pix0 % WW;
#pragma unroll
    for (int rep = 0; rep < 4; ++rep) {
        int d  = (t >> 3) + rep * 32;
        int px = t & 7;
        out[((size_t)(n0 * DIM + d) * HH + y0) * WW + x0 + px] = s_out[px][d];
    }
}

// ---------------------------------------------------------------------------
extern "C" void kernel_launch(void* const* d_in, const int* in_sizes, int n_in,
                              void* d_out, int out_size) {
    const float* feat_supp = (const float*)d_in[0];
    const float* feat_curr = (const float*)d_in[1];
    const float* flow      = (const float*)d_in[2];
    const float* q_w       = (const float*)d_in[3];
    const float* q_b       = (const float*)d_in[4];
    const float* k_w       = (const float*)d_in[5];
    const float* k_b       = (const float*)d_in[6];
    const float* v_w       = (const float*)d_in[7];
    const float* v_b       = (const float*)d_in[8];
    float* out = (float*)d_out;

    const int smem_kv = 3 * 128 * PAD * (int)sizeof(float);  // 208896 B
    const int smem_q  = 2 * 128 * PAD * (int)sizeof(float);  // 139264 B
    cudaFuncSetAttribute(gemm_kv_kernel, cudaFuncAttributeMaxDynamicSharedMemorySize, smem_kv);
    cudaFuncSetAttribute(gemm_q_kernel,  cudaFuncAttributeMaxDynamicSharedMemorySize, smem_q);

    bias_kernel<<<1, 512>>>(k_w, k_b, v_w, v_b);
    gemm_kv_kernel<<<NHW / 128, 512, smem_kv>>>(feat_supp, k_w, v_w);
    gemm_q_kernel<<<NHW / 128, 512, smem_q>>>(feat_curr, flow, q_w, q_b);
    attn_kernel<<<NHW / 8, 256>>>(flow, out);
}